// round 7
// baseline (speedup 1.0000x reference)
#include <cuda_runtime.h>

#define Bn 128
#define Tn 1024
#define Kn 16
#define STAGES 16

// Scratch (device globals: allocation-free):
__device__ float2 ELBUF[Bn * Tn * Kn];  // 16MB: (en_unnormalized, l_normalized) per (b,t,j)
__device__ float  YBUF [Bn * Tn * Kn];  // 8MB: normalized y

static __device__ __forceinline__ float ex2f(float x){ float r; asm("ex2.approx.f32 %0, %1;" : "=f"(r) : "f"(x)); return r; }
static __device__ __forceinline__ float lg2f(float x){ float r; asm("lg2.approx.f32 %0, %1;" : "=f"(r) : "f"(x)); return r; }
static __device__ __forceinline__ float rcpf(float x){ float r; asm("rcp.approx.f32 %0, %1;" : "=f"(r) : "f"(x)); return r; }
static __device__ __forceinline__ void cp16(unsigned s, const float* g){
  asm volatile("cp.async.ca.shared.global [%0], [%1], 16;" :: "r"(s), "l"(g) : "memory");
}
#define FMA2(d,a,b,c) asm("fma.rn.f32x2 %0, %1, %2, %3;" : "=l"(d) : "l"(a), "l"(b), "l"(c))
#define CBAR() asm volatile("" ::: "memory")

// ===================== kernel 1: sequential scan — pipelined, barrier-free =====================
__global__ void __launch_bounds__(32,1) scan_kernel(
 const float* __restrict__ logits, const float* __restrict__ gum)
{
  __shared__ __align__(16) float L[STAGES][Kn*Kn];  // 16KB logits ring
  __shared__ __align__(16) float G[STAGES][Kn];
  __shared__ __align__(16) float E[Kn];             // e-vector exchange buffer
  const int b = blockIdx.x;
  const int lane = threadIdx.x;
  const int j = lane & 15;                           // lanes 16..31 mirror 0..15
  const float C2L = 2.8853900817779268f;             // (1/tau)*log2(e), tau=0.5

  const float* Lb = logits + (size_t)b * Tn * 256;
  const float* Gb = gum    + (size_t)b * Tn * 16;
  float2* ELb = ELBUF + (size_t)b * Tn * Kn;
  unsigned sL0 = (unsigned)__cvta_generic_to_shared(&L[0][0]);
  unsigned sG0 = (unsigned)__cvta_generic_to_shared(&G[0][0]);

  // prologue: fill ring, ONE commit group per stage (16 groups in flight)
  #pragma unroll
  for (int s = 0; s < STAGES; ++s) {
    cp16(sL0 + s*1024 + lane*32,      Lb + s*256 + lane*8);
    cp16(sL0 + s*1024 + lane*32 + 16, Lb + s*256 + lane*8 + 4);
    if (lane < 4) cp16(sG0 + s*64 + lane*16, Gb + s*16 + lane*4);
    asm volatile("cp.async.commit_group;" ::: "memory");
  }
  // stage 0 ready -> preload Lc/gz for t=0 into registers
  asm volatile("cp.async.wait_group 15;" ::: "memory");
  float Lc[Kn], LcN[Kn];
  #pragma unroll
  for (int k = 0; k < Kn; ++k) Lc[k] = L[0][k*Kn + j];
  float gz = G[0][j] * C2L, gzN;

  float ek[Kn];
  #pragma unroll
  for (int k = 0; k < Kn; ++k) ek[k] = 1.0f;         // e=1 <=> uniform y0

  for (int t = 0; t < Tn; ++t) {
    // ---- critical chain: Lc/gz/ek already in registers ----
    float p[Kn];
    #pragma unroll
    for (int k = 0; k < Kn; ++k) p[k] = ek[k] * Lc[k];
    float u = ((((p[0]+p[1])+(p[2]+p[3]))+((p[4]+p[5])+(p[6]+p[7])))
            + (((p[8]+p[9])+(p[10]+p[11]))+((p[12]+p[13])+(p[14]+p[15]))));
    float S = ((((ek[0]+ek[1])+(ek[2]+ek[3]))+((ek[4]+ek[5])+(ek[6]+ek[7])))
            + (((ek[8]+ek[9])+(ek[10]+ek[11]))+((ek[12]+ek[13])+(ek[14]+ek[15]))));
    float r  = rcpf(S);
    float en = ex2f(fmaf(u, r * C2L, gz));           // exp((l+g)/tau)
    float l  = u * r;                                // off chain
    if (lane < Kn) E[j] = en;                        // exchange: STS ...
    CBAR();                                          // (converged warp: LSU in-order; compiler barrier only)
    float4 e0 = *(const float4*)&E[0];               // ... LDS.128 x4 reload
    float4 e1 = *(const float4*)&E[4];
    float4 e2 = *(const float4*)&E[8];
    float4 e3 = *(const float4*)&E[12];
    CBAR();
    ek[0]=e0.x; ek[1]=e0.y; ek[2]=e0.z; ek[3]=e0.w;
    ek[4]=e1.x; ek[5]=e1.y; ek[6]=e1.z; ek[7]=e1.w;
    ek[8]=e2.x; ek[9]=e2.y; ek[10]=e2.z; ek[11]=e2.w;
    ek[12]=e3.x; ek[13]=e3.y; ek[14]=e3.z; ek[15]=e3.w;
    // ---- off-chain tail: dump, prefetch t+1 operands, refill ring ----
    if (lane < Kn) ELb[t*Kn + j] = make_float2(en, l);   // 128B coalesced STG
    if (t + 1 < Tn) {
      const int sn = (t+1) & (STAGES-1);
      // slot t+1 was committed 15 groups ago -> wait_group 14 guarantees it landed;
      // these LDS issue into the ek-reload latency bubble (in-order issue, scoreboard stall at first use)
      asm volatile("cp.async.wait_group 14;" ::: "memory");
      #pragma unroll
      for (int k = 0; k < Kn; ++k) LcN[k] = L[sn][k*Kn + j];
      gzN = G[sn][j] * C2L;
      // refill the slot just consumed with data for t+16
      { int tn = t + STAGES;
        const int st = t & (STAGES-1);
        if (tn < Tn) {
          cp16(sL0 + st*1024 + lane*32,      Lb + tn*256 + lane*8);
          cp16(sL0 + st*1024 + lane*32 + 16, Lb + tn*256 + lane*8 + 4);
          if (lane < 4) cp16(sG0 + st*64 + lane*16, Gb + tn*16 + lane*4);
        }
        asm volatile("cp.async.commit_group;" ::: "memory");  // empty group ok near end
      }
      #pragma unroll
      for (int k = 0; k < Kn; ++k) Lc[k] = LcN[k];
      gz = gzN;
    }
  }
}

// ===================== kernel 2: normalize + stats (fully parallel) =====================
__global__ void __launch_bounds__(256) norm_stats(
 const float* __restrict__ trP, float* __restrict__ oLq, float* __restrict__ oLp)
{
  __shared__ float4 WP[Kn][4];                       // log(transP) rows as float4
  const float LOG2E = 1.4426950408889634f;
  const float LN2   = 0.69314718055994531f;
  const int tid = threadIdx.x;
  if (tid < 64) {
    int i = tid >> 2, q = tid & 3;
    const float* rr = trP + i*16 + q*4;
    WP[i][q] = make_float4(lg2f(rr[0])*LN2, lg2f(rr[1])*LN2,
                           lg2f(rr[2])*LN2, lg2f(rr[3])*LN2);
  }
  __syncthreads();
  const int gid = blockIdx.x * 256 + tid;            // (b,t) flattened: 131072 threads
  const float4* p = (const float4*)(ELBUF + (size_t)gid * Kn);
  float en[Kn], l[Kn];
  #pragma unroll
  for (int q = 0; q < 8; ++q) {
    float4 v = p[q];
    en[2*q] = v.x; l[2*q] = v.y; en[2*q+1] = v.z; l[2*q+1] = v.w;
  }
  float Se = 0.f;
  #pragma unroll
  for (int k = 0; k < Kn; ++k) Se += en[k];
  float r = rcpf(Se);
  float y[Kn];
  #pragma unroll
  for (int k = 0; k < Kn; ++k) y[k] = en[k] * r;
  float4* yo = (float4*)(YBUF + (size_t)gid * Kn);
  yo[0] = make_float4(y[0],y[1],y[2],y[3]);
  yo[1] = make_float4(y[4],y[5],y[6],y[7]);
  yo[2] = make_float4(y[8],y[9],y[10],y[11]);
  yo[3] = make_float4(y[12],y[13],y[14],y[15]);
  float sel = 0.f, syl = 0.f;
  #pragma unroll
  for (int k = 0; k < Kn; ++k) { sel += ex2f(l[k]*LOG2E); syl = fmaf(y[k], l[k], syl); }
  float lq = syl - lg2f(sel)*LN2;                    // sum y*(l - lse(l))
  const int t = gid & (Tn-1);
  float lp = -2.7725887222397811f;                   // t=0: -log K
  if (t) {
    const float4* pp = (const float4*)(ELBUF + (size_t)(gid-1) * Kn);
    float enp[Kn];
    #pragma unroll
    for (int q = 0; q < 8; ++q) { float4 v = pp[q]; enp[2*q] = v.x; enp[2*q+1] = v.z; }
    float Sp = 0.f;
    #pragma unroll
    for (int k = 0; k < Kn; ++k) Sp += enp[k];
    float rp = rcpf(Sp);
    float acc = 0.f;
    #pragma unroll
    for (int i = 0; i < Kn; ++i) {                   // acc = sum_i enp_i * (logP y)_i
      float4 w0 = WP[i][0], w1 = WP[i][1], w2 = WP[i][2], w3 = WP[i][3];
      float z = w0.x*y[0];
      z = fmaf(w0.y,y[1], z); z = fmaf(w0.z,y[2], z); z = fmaf(w0.w,y[3], z);
      z = fmaf(w1.x,y[4], z); z = fmaf(w1.y,y[5], z); z = fmaf(w1.z,y[6], z); z = fmaf(w1.w,y[7], z);
      z = fmaf(w2.x,y[8], z); z = fmaf(w2.y,y[9], z); z = fmaf(w2.z,y[10],z); z = fmaf(w2.w,y[11],z);
      z = fmaf(w3.x,y[12],z); z = fmaf(w3.y,y[13],z); z = fmaf(w3.z,y[14],z); z = fmaf(w3.w,y[15],z);
      acc = fmaf(enp[i], z, acc);
    }
    lp = acc * rp;
  }
  oLq[gid] = lq;
  oLp[gid] = lp;
}

// ===================== kernel 3: mixing epilogue with packed f32x2 FMA =====================
__global__ void __launch_bounds__(192) mix_kernel(
 const float* __restrict__ Am, const float* __restrict__ Bmm,
 const float* __restrict__ Cm,
 float* __restrict__ oA, float* __restrict__ oB, float* __restrict__ oC)
{
  __shared__ __align__(16) float2 ycd[32][Kn];       // y duplicated as (y,y): 4KB
  const int bid = blockIdx.x;                        // 4096 blocks
  const int b  = bid >> 5;
  const int tc = bid & 31;                           // 32-timestep chunk
  const int tid = threadIdx.x;
  const int g  = tid / 96;                           // 2 groups alternate timesteps
  const int gq = tid % 96;
  const int cols = gq * 4;
  const bool isA = cols < 256;
  unsigned long long cc0[Kn], cc1[Kn];               // packed column pairs
  #pragma unroll
  for (int k = 0; k < Kn; ++k) {
    float a,bb,cx,d;
    if (isA) { const float* s = Am + k*256 + cols;       a=s[0]; bb=s[1]; cx=s[2]; d=s[3]; }
    else     { const float* s = Bmm + k*128 + (cols-256); a=s[0]; bb=s[1]; cx=s[2]; d=s[3]; }
    asm("mov.b64 %0, {%1,%2};" : "=l"(cc0[k]) : "f"(a),  "f"(bb));
    asm("mov.b64 %0, {%1,%2};" : "=l"(cc1[k]) : "f"(cx), "f"(d));
  }
  const size_t btbase = (size_t)b * Tn + tc * 32;
  if (tid < 128) {                                   // stage duplicated y
    float4 v = ((const float4*)(YBUF + btbase * Kn))[tid];
    float2* d = &ycd[tid >> 2][(tid & 3) * 4];
    d[0] = make_float2(v.x,v.x); d[1] = make_float2(v.y,v.y);
    d[2] = make_float2(v.z,v.z); d[3] = make_float2(v.w,v.w);
  }
  __syncthreads();
  for (int ii = 0; ii < 16; ++ii) {
    const int tt = ii*2 + g;
    const ulonglong2* yr = (const ulonglong2*)&ycd[tt][0];
    unsigned long long yy[Kn];
    #pragma unroll
    for (int q = 0; q < 8; ++q) { ulonglong2 w = yr[q]; yy[2*q] = w.x; yy[2*q+1] = w.y; }
    unsigned long long a01 = 0ull, a23 = 0ull;       // (0.f,0.f)
    #pragma unroll
    for (int k = 0; k < Kn; ++k) { FMA2(a01, yy[k], cc0[k], a01); FMA2(a23, yy[k], cc1[k], a23); }
    unsigned r0,r1,r2,r3;
    asm("mov.b64 {%0,%1}, %2;" : "=r"(r0), "=r"(r1) : "l"(a01));
    asm("mov.b64 {%0,%1}, %2;" : "=r"(r2), "=r"(r3) : "l"(a23));
    float4 v = make_float4(__uint_as_float(r0), __uint_as_float(r1),
                           __uint_as_float(r2), __uint_as_float(r3));
    const size_t t = btbase + tt;
    if (isA) *(float4*)(oA + t*256 + cols) = v;
    else     *(float4*)(oB + t*128 + (cols - 256)) = v;
  }
  if (tc == 0 && tid < 128)
    ((float4*)(oC + (size_t)b*512))[tid] = ((const float4*)Cm)[tid];
}

extern "C" void kernel_launch(void* const* d_in, const int* in_sizes, int n_in,
                              void* d_out, int out_size) {
  const float* logits = (const float*)d_in[0];
  const float* gum    = (const float*)d_in[1];
  const float* Am     = (const float*)d_in[2];
  const float* Bmm    = (const float*)d_in[3];
  const float* Cm     = (const float*)d_in[4];
  const float* trP    = (const float*)d_in[5];
  float* out = (float*)d_out;
  // output layout: A_seq | B_seq | C_seq | log_qseq | log_pseq
  float* oA  = out;                               // 128*1024*256
  float* oB  = out + 33554432ull;                 // 128*1024*128
  float* oC  = out + 50331648ull;                 // 128*512
  float* oLq = out + 50397184ull;                 // 128*1024
  float* oLp = out + 50528256ull;                 // 128*1024
  scan_kernel<<<Bn, 32>>>(logits, gum);
  norm_stats<<<512, 256>>>(trP, oLq, oLp);
  mix_kernel<<<4096, 192>>>(Am, Bmm, Cm, oA, oB, oC);
}

// round 12
// speedup vs baseline: 1.2787x; 1.2787x over previous
#include <cuda_runtime.h>

#define Bn 128
#define Tn 1024
#define Kn 16
#define CHUNK 16
#define NCHK (Tn/CHUNK)

// Scratch (device globals: allocation-free):
__device__ float2 ELBUF[Bn * Tn * Kn];  // 16MB: (en_unnormalized, l_normalized) per (b,t,j)
__device__ float  YBUF [Bn * Tn * Kn];  // 8MB: normalized y

static __device__ __forceinline__ float ex2f(float x){ float r; asm("ex2.approx.f32 %0, %1;" : "=f"(r) : "f"(x)); return r; }
static __device__ __forceinline__ float lg2f(float x){ float r; asm("lg2.approx.f32 %0, %1;" : "=f"(r) : "f"(x)); return r; }
static __device__ __forceinline__ float rcpf(float x){ float r; asm("rcp.approx.f32 %0, %1;" : "=f"(r) : "f"(x)); return r; }
#define FMA2(d,a,b,c) asm("fma.rn.f32x2 %0, %1, %2, %3;" : "=l"(d) : "l"(a), "l"(b), "l"(c))
#define CBAR() asm volatile("" ::: "memory")

static __device__ __forceinline__ void mwait(unsigned mb, unsigned ph) {
  asm volatile(
    "{\n\t.reg .pred P;\n"
    "W%=:\n\tmbarrier.try_wait.parity.acquire.cta.shared::cta.b64 P, [%0], %1, 0x989680;\n"
    "\t@P bra D%=;\n\tbra W%=;\nD%=:\n\t}"
    :: "r"(mb), "r"(ph) : "memory");
}

// ===================== kernel 1: sequential scan — split-k + bulk-async =====================
__global__ void __launch_bounds__(32,1) scan_kernel(
 const float* __restrict__ logits, const float* __restrict__ gum)
{
  __shared__ __align__(16) float Ls[2][CHUNK][256];   // 32KB double-buffered logits
  __shared__ __align__(16) float Gs[2][CHUNK][16];    // 2KB gumbel
  __shared__ __align__(16) float Epar[16];            // e-vector, parity-interleaved
  __shared__ __align__(16) float2 Pp[32];             // partial-sum exchange
  __shared__ __align__(8)  unsigned long long mbar[2];

  const int b = blockIdx.x;
  const int lane = threadIdx.x;
  const int h = lane >> 4;                  // k-parity handled by this half-warp
  const int j = lane & 15;
  const float C2L = 2.8853900817779268f;    // (1/tau)*log2(e), tau=0.5

  const float* Lg = logits + (size_t)b * Tn * 256;
  const float* Gg = gum    + (size_t)b * Tn * 16;
  float2* ELb = ELBUF + (size_t)b * Tn * Kn;

  const unsigned mb0 = (unsigned)__cvta_generic_to_shared(&mbar[0]);
  const unsigned sL  = (unsigned)__cvta_generic_to_shared(&Ls[0][0][0]);
  const unsigned sG  = (unsigned)__cvta_generic_to_shared(&Gs[0][0][0]);

  // one chunk = 16 steps: 16KB logits + 1KB gumbel, one mbarrier completion
  #define ISSUE_CHUNK(c, bf) do { \
    unsigned _mb = mb0 + (unsigned)(bf)*8u; \
    asm volatile("mbarrier.arrive.expect_tx.shared.b64 _, [%0], %1;" :: "r"(_mb), "r"(17408u) : "memory"); \
    asm volatile("cp.async.bulk.shared::cluster.global.mbarrier::complete_tx::bytes [%0], [%1], %2, [%3];" \
      :: "r"(sL + (unsigned)(bf)*16384u), "l"(Lg + (size_t)(c)*CHUNK*256), "r"(16384u), "r"(_mb) : "memory"); \
    asm volatile("cp.async.bulk.shared::cluster.global.mbarrier::complete_tx::bytes [%0], [%1], %2, [%3];" \
      :: "r"(sG + (unsigned)(bf)*1024u), "l"(Gg + (size_t)(c)*CHUNK*16), "r"(1024u), "r"(_mb) : "memory"); \
  } while(0)

  if (lane == 0) {
    asm volatile("mbarrier.init.shared.b64 [%0], 1;" :: "r"(mb0)    : "memory");
    asm volatile("mbarrier.init.shared.b64 [%0], 1;" :: "r"(mb0+8u) : "memory");
    asm volatile("fence.proxy.async.shared::cta;" ::: "memory");
    ISSUE_CHUNK(0, 0);
    ISSUE_CHUNK(1, 1);
  }
  __syncwarp();

  float ekh[8];                              // e_k for k = 2m+h (this half's parity)
  #pragma unroll
  for (int m = 0; m < 8; ++m) ekh[m] = 1.0f; // e=1 <=> uniform y0

  int t = 0;
  for (int c = 0; c < NCHK; ++c) {
    const int bf = c & 1;
    mwait(mb0 + (unsigned)bf*8u, (unsigned)((c >> 1) & 1));
    const float* Lsb = &Ls[bf][0][0];
    const float* Gsb = &Gs[bf][0][0];
    #pragma unroll
    for (int i = 0; i < CHUNK; ++i, ++t) {
      // per-lane loads: 8 scalar LDS, conflict-free (parity split: h0->banks j, h1->banks 16+j)
      float Lc[8];
      #pragma unroll
      for (int m = 0; m < 8; ++m) Lc[m] = Lsb[i*256 + (2*m + h)*16 + j];
      float gz = Gsb[i*16 + j] * C2L;
      // half-warp partial sums over this parity's 8 k's
      float p[8];
      #pragma unroll
      for (int m = 0; m < 8; ++m) p[m] = ekh[m] * Lc[m];
      float pu = ((p[0]+p[1])+(p[2]+p[3])) + ((p[4]+p[5])+(p[6]+p[7]));
      float pS = ((ekh[0]+ekh[1])+(ekh[2]+ekh[3])) + ((ekh[4]+ekh[5])+(ekh[6]+ekh[7]));
      // combine with partner half (barrier-free converged-warp exchange)
      Pp[lane] = make_float2(pu, pS);
      CBAR();
      float2 q = Pp[lane ^ 16];
      CBAR();
      float u = pu + q.x;                    // full  sum_k e_k L_kj
      float S = pS + q.y;                    // full  sum_k e_k
      float r  = rcpf(S);
      float en = ex2f(fmaf(u, r * C2L, gz)); // exp((l+g)/tau)
      float l  = u * r;                      // normalized mixed logit (off chain)
      if (lane < Kn) {
        Epar[(j & 1)*8 + (j >> 1)] = en;     // parity-interleaved store
        ELb[t*Kn + j] = make_float2(en, l);  // 128B coalesced dump
      }
      CBAR();
      // reload only this parity's 8 e's: 2x LDS.128
      float4 ea = *(const float4*)&Epar[h*8];
      float4 eb = *(const float4*)&Epar[h*8 + 4];
      CBAR();
      ekh[0]=ea.x; ekh[1]=ea.y; ekh[2]=ea.z; ekh[3]=ea.w;
      ekh[4]=eb.x; ekh[5]=eb.y; ekh[6]=eb.z; ekh[7]=eb.w;
    }
    // refill this buffer with chunk c+2 (reads above all issued; DMA lands >=600cyc later)
    if (c + 2 < NCHK && lane == 0) ISSUE_CHUNK(c + 2, bf);
  }
  #undef ISSUE_CHUNK
}

// ===================== kernel 2: normalize + stats (fully parallel) =====================
__global__ void __launch_bounds__(256) norm_stats(
 const float* __restrict__ trP, float* __restrict__ oLq, float* __restrict__ oLp)
{
  __shared__ float4 WP[Kn][4];                       // log(transP) rows as float4
  const float LOG2E = 1.4426950408889634f;
  const float LN2   = 0.69314718055994531f;
  const int tid = threadIdx.x;
  if (tid < 64) {
    int i = tid >> 2, q = tid & 3;
    const float* rr = trP + i*16 + q*4;
    WP[i][q] = make_float4(lg2f(rr[0])*LN2, lg2f(rr[1])*LN2,
                           lg2f(rr[2])*LN2, lg2f(rr[3])*LN2);
  }
  __syncthreads();
  const int gid = blockIdx.x * 256 + tid;            // (b,t) flattened: 131072 threads
  const float4* p = (const float4*)(ELBUF + (size_t)gid * Kn);
  float en[Kn], l[Kn];
  #pragma unroll
  for (int q = 0; q < 8; ++q) {
    float4 v = p[q];
    en[2*q] = v.x; l[2*q] = v.y; en[2*q+1] = v.z; l[2*q+1] = v.w;
  }
  float Se = 0.f;
  #pragma unroll
  for (int k = 0; k < Kn; ++k) Se += en[k];
  float r = rcpf(Se);
  float y[Kn];
  #pragma unroll
  for (int k = 0; k < Kn; ++k) y[k] = en[k] * r;
  float4* yo = (float4*)(YBUF + (size_t)gid * Kn);
  yo[0] = make_float4(y[0],y[1],y[2],y[3]);
  yo[1] = make_float4(y[4],y[5],y[6],y[7]);
  yo[2] = make_float4(y[8],y[9],y[10],y[11]);
  yo[3] = make_float4(y[12],y[13],y[14],y[15]);
  float sel = 0.f, syl = 0.f;
  #pragma unroll
  for (int k = 0; k < Kn; ++k) { sel += ex2f(l[k]*LOG2E); syl = fmaf(y[k], l[k], syl); }
  float lq = syl - lg2f(sel)*LN2;                    // sum y*(l - lse(l))
  const int t = gid & (Tn-1);
  float lp = -2.7725887222397811f;                   // t=0: -log K
  if (t) {
    const float4* pp = (const float4*)(ELBUF + (size_t)(gid-1) * Kn);
    float enp[Kn];
    #pragma unroll
    for (int q = 0; q < 8; ++q) { float4 v = pp[q]; enp[2*q] = v.x; enp[2*q+1] = v.z; }
    float Sp = 0.f;
    #pragma unroll
    for (int k = 0; k < Kn; ++k) Sp += enp[k];
    float rp = rcpf(Sp);
    float acc = 0.f;
    #pragma unroll
    for (int i = 0; i < Kn; ++i) {                   // acc = sum_i enp_i * (logP y)_i
      float4 w0 = WP[i][0], w1 = WP[i][1], w2 = WP[i][2], w3 = WP[i][3];
      float z = w0.x*y[0];
      z = fmaf(w0.y,y[1], z); z = fmaf(w0.z,y[2], z); z = fmaf(w0.w,y[3], z);
      z = fmaf(w1.x,y[4], z); z = fmaf(w1.y,y[5], z); z = fmaf(w1.z,y[6], z); z = fmaf(w1.w,y[7], z);
      z = fmaf(w2.x,y[8], z); z = fmaf(w2.y,y[9], z); z = fmaf(w2.z,y[10],z); z = fmaf(w2.w,y[11],z);
      z = fmaf(w3.x,y[12],z); z = fmaf(w3.y,y[13],z); z = fmaf(w3.z,y[14],z); z = fmaf(w3.w,y[15],z);
      acc = fmaf(enp[i], z, acc);
    }
    lp = acc * rp;
  }
  oLq[gid] = lq;
  oLp[gid] = lp;
}

// ===================== kernel 3: mixing epilogue with packed f32x2 FMA =====================
__global__ void __launch_bounds__(192) mix_kernel(
 const float* __restrict__ Am, const float* __restrict__ Bmm,
 const float* __restrict__ Cm,
 float* __restrict__ oA, float* __restrict__ oB, float* __restrict__ oC)
{
  __shared__ __align__(16) float2 ycd[32][Kn];       // y duplicated as (y,y): 4KB
  const int bid = blockIdx.x;                        // 4096 blocks
  const int b  = bid >> 5;
  const int tc = bid & 31;                           // 32-timestep chunk
  const int tid = threadIdx.x;
  const int g  = tid / 96;                           // 2 groups alternate timesteps
  const int gq = tid % 96;
  const int cols = gq * 4;
  const bool isA = cols < 256;
  unsigned long long cc0[Kn], cc1[Kn];               // packed column pairs
  #pragma unroll
  for (int k = 0; k < Kn; ++k) {
    float a,bb,cx,d;
    if (isA) { const float* s = Am + k*256 + cols;       a=s[0]; bb=s[1]; cx=s[2]; d=s[3]; }
    else     { const float* s = Bmm + k*128 + (cols-256); a=s[0]; bb=s[1]; cx=s[2]; d=s[3]; }
    asm("mov.b64 %0, {%1,%2};" : "=l"(cc0[k]) : "f"(a),  "f"(bb));
    asm("mov.b64 %0, {%1,%2};" : "=l"(cc1[k]) : "f"(cx), "f"(d));
  }
  const size_t btbase = (size_t)b * Tn + tc * 32;
  if (tid < 128) {                                   // stage duplicated y
    float4 v = ((const float4*)(YBUF + btbase * Kn))[tid];
    float2* d = &ycd[tid >> 2][(tid & 3) * 4];
    d[0] = make_float2(v.x,v.x); d[1] = make_float2(v.y,v.y);
    d[2] = make_float2(v.z,v.z); d[3] = make_float2(v.w,v.w);
  }
  __syncthreads();
  for (int ii = 0; ii < 16; ++ii) {
    const int tt = ii*2 + g;
    const ulonglong2* yr = (const ulonglong2*)&ycd[tt][0];
    unsigned long long yy[Kn];
    #pragma unroll
    for (int q = 0; q < 8; ++q) { ulonglong2 w = yr[q]; yy[2*q] = w.x; yy[2*q+1] = w.y; }
    unsigned long long a01 = 0ull, a23 = 0ull;       // (0.f,0.f)
    #pragma unroll
    for (int k = 0; k < Kn; ++k) { FMA2(a01, yy[k], cc0[k], a01); FMA2(a23, yy[k], cc1[k], a23); }
    unsigned r0,r1,r2,r3;
    asm("mov.b64 {%0,%1}, %2;" : "=r"(r0), "=r"(r1) : "l"(a01));
    asm("mov.b64 {%0,%1}, %2;" : "=r"(r2), "=r"(r3) : "l"(a23));
    float4 v = make_float4(__uint_as_float(r0), __uint_as_float(r1),
                           __uint_as_float(r2), __uint_as_float(r3));
    const size_t t = btbase + tt;
    if (isA) *(float4*)(oA + t*256 + cols) = v;
    else     *(float4*)(oB + t*128 + (cols - 256)) = v;
  }
  if (tc == 0 && tid < 128)
    ((float4*)(oC + (size_t)b*512))[tid] = ((const float4*)Cm)[tid];
}

extern "C" void kernel_launch(void* const* d_in, const int* in_sizes, int n_in,
                              void* d_out, int out_size) {
  const float* logits = (const float*)d_in[0];
  const float* gum    = (const float*)d_in[1];
  const float* Am     = (const float*)d_in[2];
  const float* Bmm    = (const float*)d_in[3];
  const float* Cm     = (const float*)d_in[4];
  const float* trP    = (const float*)d_in[5];
  float* out = (float*)d_out;
  // output layout: A_seq | B_seq | C_seq | log_qseq | log_pseq
  float* oA  = out;                               // 128*1024*256
  float* oB  = out + 33554432ull;                 // 128*1024*128
  float* oC  = out + 50331648ull;                 // 128*512
  float* oLq = out + 50397184ull;                 // 128*1024
  float* oLp = out + 50528256ull;                 // 128*1024
  scan_kernel<<<Bn, 32>>>(logits, gum);
  norm_stats<<<512, 256>>>(trP, oLq, oLp);
  mix_kernel<<<4096, 192>>>(Am, Bmm, Cm, oA, oB, oC);
}

// round 15
// speedup vs baseline: 1.5844x; 1.2390x over previous
#include <cuda_runtime.h>

#define Bn 128
#define Tn 1024
#define Kn 16
#define CH 32
#define NCHK (Tn/CH)

static __device__ __forceinline__ float ex2f(float x){ float r; asm("ex2.approx.f32 %0, %1;" : "=f"(r) : "f"(x)); return r; }
static __device__ __forceinline__ float lg2f(float x){ float r; asm("lg2.approx.f32 %0, %1;" : "=f"(r) : "f"(x)); return r; }
static __device__ __forceinline__ float rcpf(float x){ float r; asm("rcp.approx.f32 %0, %1;" : "=f"(r) : "f"(x)); return r; }
#define FMA2(d,a,b,c) asm("fma.rn.f32x2 %0, %1, %2, %3;" : "=l"(d) : "l"(a), "l"(b), "l"(c))
#define CBAR() asm volatile("" ::: "memory")

static __device__ __forceinline__ void mwait(unsigned mb, unsigned ph) {
  asm volatile(
    "{\n\t.reg .pred P;\n"
    "W%=:\n\tmbarrier.try_wait.parity.acquire.cta.shared::cta.b64 P, [%0], %1, 0x989680;\n"
    "\t@P bra D%=;\n\tbra W%=;\nD%=:\n\t}"
    :: "r"(mb), "r"(ph) : "memory");
}

struct __align__(16) Sm {
  float  Ls[2][CH][256];      // 64KB double-buffered logits (bulk-async dst)
  float  Gs[2][CH][16];       // 4KB gumbel
  float2 ENL[2][CH][16];      // 8KB (en, l) per step, producer -> stats
  float2 YYd[2][CH][16];      // 8KB (y, y) pairs, stats -> mixers
  float  Epar[16];            // e-vector, parity-interleaved
  unsigned long long mbar[2];
};
#define SMEMSZ (sizeof(Sm))

__global__ void __launch_bounds__(256,1) fused_kernel(
 const float* __restrict__ logits, const float* __restrict__ gum,
 const float* __restrict__ Am, const float* __restrict__ Bmm,
 const float* __restrict__ Cm, const float* __restrict__ trP,
 float* __restrict__ oA, float* __restrict__ oB, float* __restrict__ oC,
 float* __restrict__ oLq, float* __restrict__ oLp)
{
  extern __shared__ char smraw[];
  Sm* sm = (Sm*)smraw;
  const int b = blockIdx.x;
  const int tid = threadIdx.x;
  const int wid = tid >> 5, lane = tid & 31;
  const int h = lane >> 4, j = lane & 15;
  const float LOG2E = 1.4426950408889634f;
  const float LN2   = 0.69314718055994531f;
  const float C2L   = 2.8853900817779268f;   // (1/tau)*log2(e), tau=0.5

  if (wid == 7) {
    // ========== producer: sequential regime scan (SMSP3, top arbiter priority) ==========
    const float* Lg = logits + (size_t)b * Tn * 256;
    const float* Gg = gum    + (size_t)b * Tn * 16;
    const unsigned mb0 = (unsigned)__cvta_generic_to_shared(&sm->mbar[0]);
    const unsigned sL  = (unsigned)__cvta_generic_to_shared(&sm->Ls[0][0][0]);
    const unsigned sG  = (unsigned)__cvta_generic_to_shared(&sm->Gs[0][0][0]);
    #define ISSUE_CHUNK(c, bf) do { \
      unsigned _mb = mb0 + (unsigned)(bf)*8u; \
      asm volatile("mbarrier.arrive.expect_tx.shared.b64 _, [%0], %1;" :: "r"(_mb), "r"(34816u) : "memory"); \
      asm volatile("cp.async.bulk.shared::cluster.global.mbarrier::complete_tx::bytes [%0], [%1], %2, [%3];" \
        :: "r"(sL + (unsigned)(bf)*32768u), "l"(Lg + (size_t)(c)*CH*256), "r"(32768u), "r"(_mb) : "memory"); \
      asm volatile("cp.async.bulk.shared::cluster.global.mbarrier::complete_tx::bytes [%0], [%1], %2, [%3];" \
        :: "r"(sG + (unsigned)(bf)*2048u), "l"(Gg + (size_t)(c)*CH*16), "r"(2048u), "r"(_mb) : "memory"); \
    } while(0)
    if (lane == 0) {
      asm volatile("mbarrier.init.shared.b64 [%0], 1;" :: "r"(mb0)    : "memory");
      asm volatile("mbarrier.init.shared.b64 [%0], 1;" :: "r"(mb0+8u) : "memory");
      asm volatile("fence.proxy.async.shared::cta;" ::: "memory");
      ISSUE_CHUNK(0, 0);
      ISSUE_CHUNK(1, 1);
    }
    __syncwarp();
    float ekh[8];
    #pragma unroll
    for (int m = 0; m < 8; ++m) ekh[m] = 1.0f;       // e=1 <=> uniform y0
    for (int c = 0; c < NCHK + 2; ++c) {
      if (c < NCHK) {
        const int bf = c & 1;
        mwait(mb0 + (unsigned)bf*8u, (unsigned)((c >> 1) & 1));
        const float* Lsb = &sm->Ls[bf][0][0];
        const float* Gsb = &sm->Gs[bf][0][0];
        #pragma unroll 8
        for (int i = 0; i < CH; ++i) {
          float Lc[8];
          #pragma unroll
          for (int m = 0; m < 8; ++m) Lc[m] = Lsb[i*256 + (2*m + h)*16 + j];
          float gz = Gsb[i*16 + j] * C2L;
          float p[8];
          #pragma unroll
          for (int m = 0; m < 8; ++m) p[m] = ekh[m] * Lc[m];
          float pu = ((p[0]+p[1])+(p[2]+p[3])) + ((p[4]+p[5])+(p[6]+p[7]));
          float pS = ((ekh[0]+ekh[1])+(ekh[2]+ekh[3])) + ((ekh[4]+ekh[5])+(ekh[6]+ekh[7]));
          float u = pu + __shfl_xor_sync(0xffffffffu, pu, 16);   // combine parities
          float S = pS + __shfl_xor_sync(0xffffffffu, pS, 16);
          float r  = rcpf(S);
          float en = ex2f(fmaf(u, r * C2L, gz));     // exp((l+g)/tau)
          float l  = u * r;
          if (lane < Kn) {
            sm->Epar[(j & 1)*8 + (j >> 1)] = en;     // parity-interleaved
            sm->ENL[bf][i][j] = make_float2(en, l);
          }
          CBAR();
          float4 ea = *(const float4*)&sm->Epar[h*8];
          float4 eb = *(const float4*)&sm->Epar[h*8 + 4];
          CBAR();
          ekh[0]=ea.x; ekh[1]=ea.y; ekh[2]=ea.z; ekh[3]=ea.w;
          ekh[4]=eb.x; ekh[5]=eb.y; ekh[6]=eb.z; ekh[7]=eb.w;
        }
        if (c + 2 < NCHK && lane == 0) ISSUE_CHUNK(c + 2, bf);
      }
      __syncthreads();
    }
    #undef ISSUE_CHUNK
  } else if (wid == 3) {
    // ========== stats: normalize + lq/lp, chunk c-1 (SMSP3, fills producer stalls) ==========
    float logPc[Kn];
    #pragma unroll
    for (int k = 0; k < Kn; ++k) logPc[k] = lg2f(trP[k*Kn + j]) * LN2;
    if (lane < Kn) sm->YYd[1][CH-1][j] = make_float2(1.0f/16.0f, 1.0f/16.0f); // t=-1 carry
    for (int c = 0; c < NCHK + 2; ++c) {
      if (c >= 1 && c <= NCHK) {
        const int sc = c - 1, sbuf = sc & 1;
        #pragma unroll 2
        for (int ii = 0; ii < 16; ++ii) {
          const int t = 2*ii + h;
          const int gt = sc*CH + t;
          float2 v = sm->ENL[sbuf][t][j];
          float en = v.x, l = v.y;
          float Se = en;
          #pragma unroll
          for (int d = 8; d; d >>= 1) Se += __shfl_xor_sync(0xffffffffu, Se, d);
          float y = en * rcpf(Se);
          sm->YYd[sbuf][t][j] = make_float2(y, y);
          CBAR();
          const int tm = t - 1;
          const float2* ypr = (tm >= 0) ? &sm->YYd[sbuf][tm][0] : &sm->YYd[sbuf^1][CH-1][0];
          float wr = 0.f;
          #pragma unroll
          for (int k = 0; k < Kn; ++k) wr = fmaf(ypr[k].x, logPc[k], wr);
          float sel = ex2f(l * LOG2E), syl = y * l, slp = y * wr;
          #pragma unroll
          for (int d = 8; d; d >>= 1) {
            sel += __shfl_xor_sync(0xffffffffu, sel, d);
            syl += __shfl_xor_sync(0xffffffffu, syl, d);
            slp += __shfl_xor_sync(0xffffffffu, slp, d);
          }
          float lq = syl - lg2f(sel) * LN2;
          float lp = (gt == 0) ? -2.7725887222397811f : slp;   // t=0: -log K
          if (j == 0) {
            oLq[(size_t)b*Tn + gt] = lq;
            oLp[(size_t)b*Tn + gt] = lp;
          }
        }
      }
      __syncthreads();
    }
  } else {
    // ========== mixers (6 warps, SMSP0-2): A_seq/B_seq for chunk c-2 ==========
    const int mw = (wid < 3) ? wid : wid - 1;        // 0..5
    const int q  = mw*32 + lane;                     // 0..191
    const int g  = q / 96;                           // alternate timesteps
    const int gq = q % 96;
    const int cols = gq * 4;
    const bool isA = cols < 256;
    unsigned long long cc0[Kn], cc1[Kn];
    #pragma unroll
    for (int k = 0; k < Kn; ++k) {
      float a,bb,cx,d;
      if (isA) { const float* s = Am + k*256 + cols;       a=s[0]; bb=s[1]; cx=s[2]; d=s[3]; }
      else     { const float* s = Bmm + k*128 + (cols-256); a=s[0]; bb=s[1]; cx=s[2]; d=s[3]; }
      asm("mov.b64 %0, {%1,%2};" : "=l"(cc0[k]) : "f"(a),  "f"(bb));
      asm("mov.b64 %0, {%1,%2};" : "=l"(cc1[k]) : "f"(cx), "f"(d));
    }
    for (int c = 0; c < NCHK + 2; ++c) {
      if (c >= 2) {
        const int mc = c - 2, mbuf = mc & 1;
        const size_t tbase = (size_t)b * Tn + mc*CH;
        #pragma unroll 2
        for (int ii = 0; ii < 16; ++ii) {
          const int tt = 2*ii + g;
          const ulonglong2* yr = (const ulonglong2*)&sm->YYd[mbuf][tt][0];
          unsigned long long yy[Kn];
          #pragma unroll
          for (int qq = 0; qq < 8; ++qq) { ulonglong2 w = yr[qq]; yy[2*qq] = w.x; yy[2*qq+1] = w.y; }
          unsigned long long a01 = 0ull, a23 = 0ull;
          #pragma unroll
          for (int k = 0; k < Kn; ++k) { FMA2(a01, yy[k], cc0[k], a01); FMA2(a23, yy[k], cc1[k], a23); }
          unsigned r0,r1,r2,r3;
          asm("mov.b64 {%0,%1}, %2;" : "=r"(r0), "=r"(r1) : "l"(a01));
          asm("mov.b64 {%0,%1}, %2;" : "=r"(r2), "=r"(r3) : "l"(a23));
          float4 v = make_float4(__uint_as_float(r0), __uint_as_float(r1),
                                 __uint_as_float(r2), __uint_as_float(r3));
          const size_t t = tbase + tt;
          if (isA) *(float4*)(oA + t*256 + cols) = v;
          else     *(float4*)(oB + t*128 + (cols - 256)) = v;
        }
      }
      __syncthreads();
    }
  }
  // C_seq: per-batch copy of Cm (512 floats)
  if (tid < 128)
    ((float4*)(oC + (size_t)b*512))[tid] = ((const float4*)Cm)[tid];
}

extern "C" void kernel_launch(void* const* d_in, const int* in_sizes, int n_in,
                              void* d_out, int out_size) {
  const float* logits = (const float*)d_in[0];
  const float* gum    = (const float*)d_in[1];
  const float* Am     = (const float*)d_in[2];
  const float* Bmm    = (const float*)d_in[3];
  const float* Cm     = (const float*)d_in[4];
  const float* trP    = (const float*)d_in[5];
  float* out = (float*)d_out;
  // output layout: A_seq | B_seq | C_seq | log_qseq | log_pseq
  float* oA  = out;                               // 128*1024*256
  float* oB  = out + 33554432ull;                 // 128*1024*128
  float* oC  = out + 50331648ull;                 // 128*512
  float* oLq = out + 50397184ull;                 // 128*1024
  float* oLp = out + 50528256ull;                 // 128*1024
  // one-time opt-in to >48KB dynamic smem (runs on the pre-capture correctness call)
  static bool smem_ok = []() {
    cudaFuncSetAttribute(fused_kernel, cudaFuncAttributeMaxDynamicSharedMemorySize, (int)SMEMSZ);
    return true;
  }();
  (void)smem_ok;
  fused_kernel<<<Bn, 256, SMEMSZ>>>(logits, gum, Am, Bmm, Cm, trP, oA, oB, oC, oLq, oLp);
}